// round 3
// baseline (speedup 1.0000x reference)
#include <cuda_runtime.h>

// Problem constants (fixed shapes per reference setup_inputs)
#define NROWS 2048
#define NCOLS 9605
#define NTOT  (NROWS * NCOLS)        // 19,671,040 (divisible by 4)
#define N4    (NTOT / 4)
#define CAP   256
#define CLIPV 0.05f
#define P_TH  0.90f                   // sigmoid(2.197); E[cands/row] ~ 134

__device__ double g_accum;
__device__ int    g_cnt[NROWS];                      // reset every launch
__device__ unsigned long long g_cand[(size_t)NROWS * CAP];   // 4 MiB

// ---------------------------------------------------------------------------
__global__ void k_init() {
    int i = blockIdx.x * blockDim.x + threadIdx.x;
    if (i == 0) g_accum = 0.0;
    if (i < NROWS) g_cnt[i] = 0;
}

// base * w for one element (matches reference formulas; y in {0,1})
__device__ __forceinline__ float bw_of(float xv, float yv, float& p_out) {
    float e    = __expf(-xv);
    float p    = __fdividef(1.f, 1.f + e);          // sigmoid
    p_out      = p;
    float xneg = fminf(1.f - p + CLIPV, 1.f);       // clipped negative prob
    float t    = fmaxf(p - CLIPV, 0.f);             // = 1 - xneg
    float t2   = t * t;
    float t4   = t2 * t2;                            // (1-pt)^4 for y=0
    bool  pos  = yv > 0.5f;
    float lg   = __logf(fmaxf(pos ? p : xneg, 1e-8f));
    float w    = pos ? (1.f - p) : t4;               // gamma_pos=1, gamma_neg=4
    return lg * w;
}

// ---------------------------------------------------------------------------
// Kernel A: flat float4 streaming pass — global sum of base*w, and candidate
// harvest (p > P_TH) for per-row top-10.
__global__ void __launch_bounds__(256) k_main(const float* __restrict__ x,
                                              const float* __restrict__ y) {
    const float4* __restrict__ x4 = reinterpret_cast<const float4*>(x);
    const float4* __restrict__ y4 = reinterpret_cast<const float4*>(y);
    const int stride = gridDim.x * 256;
    float sum = 0.f;

    for (int v = blockIdx.x * 256 + threadIdx.x; v < N4; v += stride) {
        float4 xv = x4[v];
        float4 yv = y4[v];
        int base = v * 4;
        float xs[4] = {xv.x, xv.y, xv.z, xv.w};
        float ys[4] = {yv.x, yv.y, yv.z, yv.w};
#pragma unroll
        for (int k = 0; k < 4; k++) {
            float p;
            sum += bw_of(xs[k], ys[k], p);
            if (p > P_TH) {                                  // rare (~1.4%)
                int gi  = base + k;
                int row = gi / NCOLS;                        // const-div -> mulhi
                int col = gi - row * NCOLS;
                unsigned long long key =
                    ((unsigned long long)__float_as_uint(p) << 32) |
                    (unsigned long long)(0xFFFFFFFFu - (unsigned)col);
                int slot = atomicAdd(&g_cnt[row], 1);
                if (slot < CAP)
                    g_cand[(size_t)row * CAP + slot] = key;
            }
        }
    }

    // block reduction -> double atomic
#pragma unroll
    for (int off = 16; off > 0; off >>= 1)
        sum += __shfl_down_sync(0xFFFFFFFFu, sum, off);
    __shared__ float sp[8];
    int lane = threadIdx.x & 31, wid = threadIdx.x >> 5;
    if (lane == 0) sp[wid] = sum;
    __syncthreads();
    if (threadIdx.x == 0) {
        float b = 0.f;
#pragma unroll
        for (int i = 0; i < 8; i++) b += sp[i];
        atomicAdd(&g_accum, (double)b);
    }
}

// ---------------------------------------------------------------------------
__device__ __forceinline__ void insert10(unsigned long long* tp,
                                         unsigned long long key) {
    if (key > tp[9]) {
        tp[9] = key;
#pragma unroll
        for (int i = 9; i > 0; i--) {
            if (tp[i] > tp[i - 1]) {
                unsigned long long tmp = tp[i - 1];
                tp[i - 1] = tp[i];
                tp[i] = tmp;
            }
        }
    }
}

// Kernel B: per-row — gt-whitelist flags, exact top-10, sequential rank
// multiplier logic, corrections bw_j * (mult_j - 1), counter reset.
__global__ void __launch_bounds__(192) k_topk(const float* __restrict__ x,
                                              const float* __restrict__ y,
                                              const int* __restrict__ ci,
                                              const int* __restrict__ ri,
                                              const int* __restrict__ di,
                                              const int* __restrict__ wl) {
    const int row = blockIdx.x, tid = threadIdx.x;
    __shared__ int s_flags[3];
    __shared__ unsigned long long s_cand[CAP];
    __shared__ int   s_idx[10];
    __shared__ float s_factor[10];
    __shared__ int   s_found;

    const float* __restrict__ xr = x + (size_t)row * NCOLS;
    const float* __restrict__ yr = y + (size_t)row * NCOLS;

    if (tid < 3) s_flags[tid] = 0;
    __syncthreads();

    if (tid < 30)       { if (yr[ci[tid]]       > 0.5f) atomicOr(&s_flags[0], 1); }
    else if (tid < 100) { if (yr[ri[tid - 30]]  > 0.5f) atomicOr(&s_flags[1], 1); }
    else if (tid < 170) { if (yr[di[tid - 100]] > 0.5f) atomicOr(&s_flags[2], 1); }

    int n = g_cnt[row];
    int m = n < CAP ? n : CAP;
    for (int i = tid; i < m; i += 192)
        s_cand[i] = g_cand[(size_t)row * CAP + i];
    __syncthreads();

    if (tid == 0) {
        unsigned long long tp[10];
#pragma unroll
        for (int i = 0; i < 10; i++) tp[i] = 0ULL;

        if (n < 10 || n > CAP) {
            // exact (correct-for-any-input) fallback: full serial row scan
            for (int c = 0; c < NCOLS; c++) {
                float e = __expf(-xr[c]);
                float p = __fdividef(1.f, 1.f + e);
                unsigned long long key =
                    ((unsigned long long)__float_as_uint(p) << 32) |
                    (unsigned long long)(0xFFFFFFFFu - (unsigned)c);
                insert10(tp, key);
            }
        } else {
            for (int i = 0; i < m; i++) insert10(tp, s_cand[i]);
        }

        // sequential rank logic over the 10 ranks (order matters)
        bool has1 = s_flags[0] != 0, has2 = s_flags[1] != 0, has3 = s_flags[2] != 0;
        bool only4 = !(has1 || has2 || has3);
        bool found = false;
#pragma unroll
        for (int r = 0; r < 10; r++) {
            int j = (int)(0xFFFFFFFFu - (unsigned)(tp[r] & 0xFFFFFFFFULL));
            int g = wl[j];
            bool in_map = g > 0;
            bool in_gt  = ((g == 1) && has1) || ((g == 2) && has2) ||
                          ((g == 3) && has3) || ((g == 4) && only4);
            float f = (in_map && only4) ? 0.5f : 1.f;            // ALPHA_OTHER
            if (in_map && !in_gt && !found) f *= 2.f;            // ALPHA1
            s_idx[r] = j;
            s_factor[r] = f;
            found = found || (in_map && in_gt);
        }
        s_found = found ? 1 : 0;
        g_cnt[row] = 0;   // reset for next graph replay (deterministic)
    }
    __syncthreads();

    float corr = 0.f;
    if (tid < 10) {
        int j = s_idx[tid];
        float mult = s_factor[tid] * (s_found ? 1.f : 2.f);      // extra ALPHA1
        float p;
        float bw = bw_of(xr[j], yr[j], p);
        corr = bw * (mult - 1.f);
    }
    if (tid < 32) {
#pragma unroll
        for (int off = 16; off > 0; off >>= 1)
            corr += __shfl_down_sync(0xFFFFFFFFu, corr, off);
        if (tid == 0) atomicAdd(&g_accum, (double)corr);
    }
}

// ---------------------------------------------------------------------------
__global__ void k_fin(float* out) { out[0] = (float)(-g_accum); }

extern "C" void kernel_launch(void* const* d_in, const int* in_sizes, int n_in,
                              void* d_out, int out_size) {
    const float* x  = (const float*)d_in[0];
    const float* y  = (const float*)d_in[1];
    const int*   ci = (const int*)d_in[2];
    const int*   ri = (const int*)d_in[3];
    const int*   di = (const int*)d_in[4];
    const int*   wl = (const int*)d_in[5];

    k_init<<<(NROWS + 255) / 256, 256>>>();
    k_main<<<2048, 256>>>(x, y);
    k_topk<<<NROWS, 192>>>(x, y, ci, ri, di, wl);
    k_fin<<<1, 1>>>((float*)d_out);
}

// round 7
// speedup vs baseline: 1.2903x; 1.2903x over previous
#include <cuda_runtime.h>

#define NROWS   2048
#define NCOLS   9605
#define ROWS_PB 4
#define NBLK    (NROWS / ROWS_PB)          // 512
#define V4_PB   (ROWS_PB * NCOLS / 4)      // 9605 float4s per block (exact)
#define CAPS    320
#define CLIPV   0.05f
#define P_TH    0.90f                       // sigmoid(2.197); E[cand/row] ~134

__device__ double g_part[NBLK];

// base*w for one element; returns bw, outputs sigmoid p
__device__ __forceinline__ float bw_of(float xv, float yv, float& p_out) {
    float e    = __expf(-xv);
    float p    = __fdividef(1.f, 1.f + e);
    p_out      = p;
    float xneg = fminf(1.f - p + CLIPV, 1.f);
    float t    = fmaxf(p - CLIPV, 0.f);          // 1 - xneg
    float t2   = t * t;
    float t4   = t2 * t2;
    bool  pos  = yv > 0.5f;
    float lg   = __logf(fmaxf(pos ? p : xneg, 1e-8f));
    float w    = pos ? (1.f - p) : t4;           // gamma_pos=1, gamma_neg=4
    return lg * w;
}

__device__ __forceinline__ unsigned long long mk_key(float p, int col) {
    return ((unsigned long long)__float_as_uint(p) << 32) |
           (unsigned long long)(0xFFFFFFFFu - (unsigned)col);
}

// insert (key, payload bw) into descending top-10 arrays
__device__ __forceinline__ void ins10(unsigned long long* tk, float* tb,
                                      unsigned long long key, float bw) {
    if (key > tk[9]) {
        tk[9] = key; tb[9] = bw;
#pragma unroll
        for (int i = 9; i > 0; i--) {
            if (tk[i] > tk[i - 1]) {
                unsigned long long k0 = tk[i - 1]; tk[i - 1] = tk[i]; tk[i] = k0;
                float b0 = tb[i - 1]; tb[i - 1] = tb[i]; tb[i] = b0;
            }
        }
    }
}

// ---------------------------------------------------------------------------
// One block = 4 rows: stream sum + candidate harvest (smem) + flags + top-10 +
// rank multiplier corrections. Writes one double partial per block.
__global__ void __launch_bounds__(256)
k_main(const float* __restrict__ x, const float* __restrict__ y,
       const int* __restrict__ ci, const int* __restrict__ ri,
       const int* __restrict__ di, const int* __restrict__ wl) {
    const int tid = threadIdx.x;
    const int row0 = blockIdx.x * ROWS_PB;
    const size_t base = (size_t)row0 * NCOLS;

    __shared__ int                s_cnt[ROWS_PB];
    __shared__ int                s_flags[ROWS_PB];
    __shared__ unsigned long long s_key[ROWS_PB][CAPS + 1];
    __shared__ float              s_bw[ROWS_PB][CAPS + 1];
    __shared__ float              s_corr[ROWS_PB];
    __shared__ float              s_warp[8];

    if (tid < ROWS_PB) { s_cnt[tid] = 0; s_flags[tid] = 0; }
    __syncthreads();

    const float4* __restrict__ x4 = reinterpret_cast<const float4*>(x + base);
    const float4* __restrict__ y4 = reinterpret_cast<const float4*>(y + base);

    float sum = 0.f;
#pragma unroll 2
    for (int v = tid; v < V4_PB; v += 256) {
        float4 xv = x4[v];
        float4 yv = y4[v];
        float xs[4] = {xv.x, xv.y, xv.z, xv.w};
        float ys[4] = {yv.x, yv.y, yv.z, yv.w};
        int gi0 = v * 4;
#pragma unroll
        for (int k = 0; k < 4; k++) {
            float p;
            float bw = bw_of(xs[k], ys[k], p);
            sum += bw;
            if (p > P_TH) {                               // ~1.4% of elements
                int gi = gi0 + k;
                int rl = gi / NCOLS;                      // 0..3 (const div)
                int col = gi - rl * NCOLS;
                int slot = atomicAdd(&s_cnt[rl], 1);
                if (slot < CAPS) {
                    s_key[rl][slot] = mk_key(p, col);
                    s_bw[rl][slot]  = bw;
                }
            }
        }
    }

    // gt-whitelist flags: 170 probe indices x 4 rows (reads hit L2-hot rows)
    for (int i = tid; i < 170 * ROWS_PB; i += 256) {
        int r = i / 170, k = i - r * 170;
        int idx = (k < 30) ? ci[k] : (k < 100) ? ri[k - 30] : di[k - 100];
        if (y[base + (size_t)r * NCOLS + idx] > 0.5f) {
            int bit = (k < 30) ? 1 : (k < 100) ? 2 : 4;
            atomicOr(&s_flags[r], bit);
        }
    }
    __syncthreads();

    // per-row selection + rank logic (threads 0..3, one row each)
    if (tid < ROWS_PB) {
        const int r = tid;
        unsigned long long tk[10];
        float tb[10];
#pragma unroll
        for (int i = 0; i < 10; i++) { tk[i] = 0ULL; tb[i] = 0.f; }

        int n = s_cnt[r];
        if (n < 10 || n > CAPS) {
            // exact fallback: serial rescan of the row (astronomically rare)
            const float* xr = x + base + (size_t)r * NCOLS;
            const float* yr = y + base + (size_t)r * NCOLS;
            for (int c = 0; c < NCOLS; c++) {
                float p;
                float bw = bw_of(xr[c], yr[c], p);
                ins10(tk, tb, mk_key(p, c), bw);
            }
        } else {
            for (int i = 0; i < n; i++) ins10(tk, tb, s_key[r][i], s_bw[r][i]);
        }

        int fl = s_flags[r];
        bool has1 = fl & 1, has2 = fl & 2, has3 = fl & 4;
        bool only4 = !(has1 || has2 || has3);
        bool found = false;
        float fac[10];
#pragma unroll
        for (int q = 0; q < 10; q++) {
            int j = (int)(0xFFFFFFFFu - (unsigned)(tk[q] & 0xFFFFFFFFULL));
            int g = wl[j];
            bool in_map = g > 0;
            bool in_gt  = ((g == 1) && has1) || ((g == 2) && has2) ||
                          ((g == 3) && has3) || ((g == 4) && only4);
            float f = (in_map && only4) ? 0.5f : 1.f;     // ALPHA_OTHER
            if (in_map && !in_gt && !found) f *= 2.f;     // ALPHA1 (first-miss)
            fac[q] = f;
            found = found || (in_map && in_gt);
        }
        float extra = found ? 1.f : 2.f;                  // final ALPHA1 pass
        float corr = 0.f;
#pragma unroll
        for (int q = 0; q < 10; q++)
            corr += tb[q] * (fac[q] * extra - 1.f);       // bw*(mult-1)
        s_corr[r] = corr;
    }

    // block reduction of stream sum + corrections -> double partial
#pragma unroll
    for (int off = 16; off > 0; off >>= 1)
        sum += __shfl_down_sync(0xFFFFFFFFu, sum, off);
    int lane = tid & 31, wid = tid >> 5;
    if (lane == 0) s_warp[wid] = sum;
    __syncthreads();
    if (tid == 0) {
        float b = 0.f;
#pragma unroll
        for (int i = 0; i < 8; i++) b += s_warp[i];
        double tot = (double)b;
#pragma unroll
        for (int r = 0; r < ROWS_PB; r++) tot += (double)s_corr[r];
        g_part[blockIdx.x] = tot;
    }
}

// ---------------------------------------------------------------------------
__global__ void __launch_bounds__(256) k_fin(float* out) {
    int tid = threadIdx.x;
    double d = g_part[tid] + g_part[tid + 256];
#pragma unroll
    for (int off = 16; off > 0; off >>= 1)
        d += __shfl_down_sync(0xFFFFFFFFu, d, off);
    __shared__ double sw[8];
    int lane = tid & 31, wid = tid >> 5;
    if (lane == 0) sw[wid] = d;
    __syncthreads();
    if (tid == 0) {
        double t = 0.0;
#pragma unroll
        for (int i = 0; i < 8; i++) t += sw[i];
        out[0] = (float)(-t);
    }
}

extern "C" void kernel_launch(void* const* d_in, const int* in_sizes, int n_in,
                              void* d_out, int out_size) {
    const float* x  = (const float*)d_in[0];
    const float* y  = (const float*)d_in[1];
    const int*   ci = (const int*)d_in[2];
    const int*   ri = (const int*)d_in[3];
    const int*   di = (const int*)d_in[4];
    const int*   wl = (const int*)d_in[5];

    k_main<<<NBLK, 256>>>(x, y, ci, ri, di, wl);
    k_fin<<<1, 256>>>((float*)d_out);
}